// round 6
// baseline (speedup 1.0000x reference)
#include <cuda_runtime.h>
#include <cstdint>

#define N_MAX 100000
#define E_MAX 1600000
#define NBLK_SCAN 128   // max scan blocks (n/1024 <= 98)
#define AGG_NPB 8       // nodes per agg block (one warp per node)

// ---------------- scratch (static device memory; no allocation) ----------------
__device__ int   g_deg_out[N_MAX];
__device__ int   g_deg_in[N_MAX];
__device__ float g_norm_src[N_MAX];
__device__ float g_norm_dst[N_MAX];
__device__ int   g_row_ptr[N_MAX + 1];
__device__ int   g_fill[N_MAX];
__device__ int   g_col[E_MAX];
__device__ float g_a[N_MAX * 64];   // ping: pre-scaled features (norm_src * h)
__device__ float g_b[N_MAX * 64];   // pong
__device__ int g_blk_sum[NBLK_SCAN];
__device__ volatile int g_blk_flag[NBLK_SCAN];

// ---------------- threefry-2x32 (exact JAX algorithm, partitionable path) ----------------
__device__ __forceinline__ void d_threefry(uint32_t k0, uint32_t k1,
                                           uint32_t x0, uint32_t x1,
                                           uint32_t& y0, uint32_t& y1) {
    uint32_t k2 = k0 ^ k1 ^ 0x1BD11BDAu;
    x0 += k0; x1 += k1;
#define TFR(r) { x0 += x1; x1 = __funnelshift_l(x1, x1, r); x1 ^= x0; }
    TFR(13) TFR(15) TFR(26) TFR(6)
    x0 += k1; x1 += k2 + 1u;
    TFR(17) TFR(29) TFR(16) TFR(24)
    x0 += k2; x1 += k0 + 2u;
    TFR(13) TFR(15) TFR(26) TFR(6)
    x0 += k0; x1 += k1 + 3u;
    TFR(17) TFR(29) TFR(16) TFR(24)
    x0 += k1; x1 += k2 + 4u;
    TFR(13) TFR(15) TFR(26) TFR(6)
    x0 += k2; x1 += k0 + 5u;
#undef TFR
    y0 = x0; y1 = x1;
}

static inline uint32_t h_rotl(uint32_t x, int r) { return (x << r) | (x >> (32 - r)); }
static void h_threefry(uint32_t k0, uint32_t k1, uint32_t x0, uint32_t x1,
                       uint32_t& y0, uint32_t& y1) {
    uint32_t k2 = k0 ^ k1 ^ 0x1BD11BDAu;
    x0 += k0; x1 += k1;
#define TFR(r) { x0 += x1; x1 = h_rotl(x1, r); x1 ^= x0; }
    TFR(13) TFR(15) TFR(26) TFR(6)
    x0 += k1; x1 += k2 + 1u;
    TFR(17) TFR(29) TFR(16) TFR(24)
    x0 += k2; x1 += k0 + 2u;
    TFR(13) TFR(15) TFR(26) TFR(6)
    x0 += k0; x1 += k1 + 3u;
    TFR(17) TFR(29) TFR(16) TFR(24)
    x0 += k1; x1 += k2 + 4u;
    TFR(13) TFR(15) TFR(26) TFR(6)
    x0 += k2; x1 += k0 + 5u;
#undef TFR
    y0 = x0; y1 = x1;
}

// ---------------- graph prep ----------------
__global__ void k_zero(int n) {
    int i = blockIdx.x * blockDim.x + threadIdx.x;
    if (i < n) { g_deg_out[i] = 0; g_deg_in[i] = 0; }
    if (i < NBLK_SCAN) { g_blk_flag[i] = 0; g_blk_sum[i] = 0; }
}

__global__ void k_degree(const int* __restrict__ src, const int* __restrict__ dst, int e) {
    int i = blockIdx.x * blockDim.x + threadIdx.x;
    if (i < e) {
        atomicAdd(&g_deg_out[src[i]], 1);
        atomicAdd(&g_deg_in[dst[i]], 1);
    }
}

// fused: norms + single-pass exclusive scan (decoupled lookback) -> row_ptr / fill
__global__ void k_scan_norm(int n, int e) {
    __shared__ int s[1024];
    __shared__ int s_prefix;
    int b = blockIdx.x, t = threadIdx.x, i = b * 1024 + t;
    int din = (i < n) ? g_deg_in[i] : 0;
    if (i < n) {
        int a = g_deg_out[i];
        g_norm_src[i] = (a > 0) ? rsqrtf((float)a) : 0.f;
        g_norm_dst[i] = (din > 0) ? rsqrtf((float)din) : 0.f;
    }
    s[t] = din;
    __syncthreads();
    for (int off = 1; off < 1024; off <<= 1) {
        int a = (t >= off) ? s[t - off] : 0;
        __syncthreads();
        s[t] += a;
        __syncthreads();
    }
    if (t == 0) {
        s_prefix = 0;
        g_blk_sum[b] = s[1023];
        __threadfence();
        g_blk_flag[b] = 1;
    }
    __syncthreads();
    if (t < b) {
        while (g_blk_flag[t] == 0) {}
        int v = *((volatile int*)&g_blk_sum[t]);
        atomicAdd(&s_prefix, v);
    }
    __syncthreads();
    int excl = s[t] - din + s_prefix;
    if (i < n) { g_row_ptr[i] = excl; g_fill[i] = excl; }
    if (i == 0) g_row_ptr[n] = e;
}

__global__ void k_csr(const int* __restrict__ src, const int* __restrict__ dst, int e) {
    int i = blockIdx.x * blockDim.x + threadIdx.x;
    if (i < e) {
        int p = atomicAdd(&g_fill[dst[i]], 1);
        g_col[p] = src[i];
    }
}

// U0 = norm_src * x   (float4 elementwise)
__global__ void k_scale_x(const float* __restrict__ x, int n16) {
    int i = blockIdx.x * blockDim.x + threadIdx.x;
    if (i < n16) {
        float ns = g_norm_src[i >> 4];
        float4 v = ((const float4*)x)[i];
        v.x *= ns; v.y *= ns; v.z *= ns; v.w *= ns;
        ((float4*)g_a)[i] = v;
    }
}

// ---------------- packed f32x2 helpers ----------------
__device__ __forceinline__ unsigned long long pk2(float x, float y) {
    unsigned long long r;
    asm("mov.b64 %0, {%1,%2};" : "=l"(r) : "f"(x), "f"(y));
    return r;
}
__device__ __forceinline__ void fma2(unsigned long long& d, unsigned long long a, unsigned long long b) {
    asm("fma.rn.f32x2 %0, %1, %2, %0;" : "+l"(d) : "l"(a), "l"(b));
}
__device__ __forceinline__ float2 upk2(unsigned long long v) {
    float2 r;
    asm("mov.b64 {%0,%1}, %2;" : "=f"(r.x), "=f"(r.y) : "l"(v));
    return r;
}

// ---------------- fused aggregation + GEMV + epilogue ----------------
// Per layer: S[v] = sum_{u in N(v)} U[u]        (U pre-scaled by norm_src)
//            out[v] = norm_dst[v] * (S[v] @ W) + b ; relu; dropout (layers 0,1)
//            write:  layers 0,1 -> Unext = norm_src * out ; layer 2 -> d_out
// Block: 8 nodes, warp per node. Phase 1 gather (lane = col pair),
// phase 2 stage S in smem, phase 3 GEMV vs smem W, phase 4 epilogue.
template <int LAYER>
__global__ void __launch_bounds__(256) k_aggemm(const float* __restrict__ U,
                                                float* __restrict__ Unext,
                                                const float* __restrict__ W,
                                                const float* __restrict__ bias,
                                                uint32_t key0, uint32_t key1, int n) {
    __shared__ unsigned long long sW[64 * 32]; // [k][cpair] packed (W[k][2c], W[k][2c+1])
    __shared__ float sS[AGG_NPB][64];
    int t = threadIdx.x;
    int base = blockIdx.x * AGG_NPB;
    int w = t >> 5, lane = t & 31;
    int node = base + w;

    // stage W (16KB, 8 x float2 per thread)
    const float2* Wv = (const float2*)W;
#pragma unroll
    for (int q = 0; q < 8; q++) {
        int idx = t + q * 256;
        float2 wv = Wv[idx];
        sW[idx] = pk2(wv.x, wv.y);
    }

    // phase 1: gather-sum (direct col loads, R3 style)
    float ax = 0.f, ay = 0.f;
    if (node < n) {
        int s = g_row_ptr[node], e = g_row_ptr[node + 1];
        const float2* T2 = (const float2*)U;
        int i = s;
        for (; i + 4 <= e; i += 4) {
            int u0 = g_col[i], u1 = g_col[i + 1], u2 = g_col[i + 2], u3 = g_col[i + 3];
            float2 v0 = T2[u0 * 32 + lane];
            float2 v1 = T2[u1 * 32 + lane];
            float2 v2 = T2[u2 * 32 + lane];
            float2 v3 = T2[u3 * 32 + lane];
            ax += (v0.x + v1.x) + (v2.x + v3.x);
            ay += (v0.y + v1.y) + (v2.y + v3.y);
        }
        for (; i < e; i++) {
            int u = g_col[i];
            float2 v = T2[u * 32 + lane];
            ax += v.x; ay += v.y;
        }
    }
    // phase 2: stage S
    ((float2*)sS[w])[lane] = make_float2(ax, ay);
    __syncthreads();

    // phase 3: GEMV. thread -> (node w2, col pair c): out[2c,2c+1] = sum_k S[k] * W[k][2c..]
    int w2 = t >> 5;       // node within block
    int c  = t & 31;       // col pair
    int node2 = base + w2;
    unsigned long long acc = 0ull;
    const float* Srow = sS[w2];
#pragma unroll 8
    for (int k = 0; k < 64; k++) {
        float sv = Srow[k];
        fma2(acc, pk2(sv, sv), sW[k * 32 + c]);
    }

    // phase 4: epilogue
    if (node2 < n) {
        float nd = g_norm_dst[node2];
        float2 bb = ((const float2*)bias)[c];
        float2 v = upk2(acc);
        float ox = v.x * nd + bb.x;
        float oy = v.y * nd + bb.y;
        if (LAYER != 2) {
            ox = fmaxf(ox, 0.f);
            oy = fmaxf(oy, 0.f);
            uint32_t idx = (uint32_t)node2 * 64u + 2u * (uint32_t)c;
            uint32_t y0, y1;
            d_threefry(key0, key1, 0u, idx, y0, y1);
            bool keep0 = (((y0 ^ y1) >> 31) == 0u);
            d_threefry(key0, key1, 0u, idx + 1u, y0, y1);
            bool keep1 = (((y0 ^ y1) >> 31) == 0u);
            float ns = g_norm_src[node2];   // pre-scale for next layer's gather
            ox = keep0 ? ox * 2.f * ns : 0.f;
            oy = keep1 ? oy * 2.f * ns : 0.f;
        }
        ((float2*)Unext)[node2 * 32 + c] = make_float2(ox, oy);
    }
}

// ---------------- launch ----------------
extern "C" void kernel_launch(void* const* d_in, const int* in_sizes, int n_in,
                              void* d_out, int out_size) {
    const float* x  = (const float*)d_in[0];
    const float* W0 = (const float*)d_in[1];
    const float* b0 = (const float*)d_in[2];
    const float* W1 = (const float*)d_in[3];
    const float* b1 = (const float*)d_in[4];
    const float* W2 = (const float*)d_in[5];
    const float* b2 = (const float*)d_in[6];
    const int*   src = (const int*)d_in[7];
    const int*   dst = (const int*)d_in[8];
    int n = in_sizes[0] / 64;
    int e = in_sizes[7];
    float* out = (float*)d_out;

    int nb = (n + 1023) / 1024;  // <= 98: all scan blocks resident, lookback safe

    uint32_t d0k0, d0k1, d1k0, d1k1;
    h_threefry(0u, 1u, 0u, 0u, d0k0, d0k1);
    h_threefry(0u, 1u, 0u, 1u, d1k0, d1k1);

    float* gA; cudaGetSymbolAddress((void**)&gA, g_a);
    float* gB; cudaGetSymbolAddress((void**)&gB, g_b);

    int aB = (n + AGG_NPB - 1) / AGG_NPB;

    k_zero<<<(n + 255) / 256, 256>>>(n);
    k_degree<<<(e + 255) / 256, 256>>>(src, dst, e);
    k_scan_norm<<<nb, 1024>>>(n, e);
    k_csr<<<(e + 255) / 256, 256>>>(src, dst, e);
    k_scale_x<<<(n * 16 + 255) / 256, 256>>>(x, n * 16);

    k_aggemm<0><<<aB, 256>>>(gA, gB, W0, b0, d0k0, d0k1, n);
    k_aggemm<1><<<aB, 256>>>(gB, gA, W1, b1, d1k0, d1k1, n);
    k_aggemm<2><<<aB, 256>>>(gA, out, W2, b2, 0u, 0u, n);
}

// round 7
// speedup vs baseline: 1.2883x; 1.2883x over previous
#include <cuda_runtime.h>
#include <cstdint>

#define N_MAX 100000
#define E_MAX 1600000
#define NBLK_SCAN 128   // max scan blocks (n/1024 <= 98)
#define AGG_NPB 64      // nodes per fused block
#define SS_STRIDE 66    // padded row stride for sS (floats)

// ---------------- scratch (static device memory; no allocation) ----------------
__device__ int   g_deg_out[N_MAX];
__device__ int   g_deg_in[N_MAX];
__device__ float g_norm_src[N_MAX];
__device__ float g_norm_dst[N_MAX];
__device__ int   g_row_ptr[N_MAX + 1];
__device__ int   g_fill[N_MAX];
__device__ int   g_col[E_MAX];
__device__ float g_a[N_MAX * 64];   // ping: pre-scaled features (norm_src * h)
__device__ float g_b[N_MAX * 64];   // pong
__device__ int g_blk_sum[NBLK_SCAN];
__device__ volatile int g_blk_flag[NBLK_SCAN];

// ---------------- threefry-2x32 (exact JAX algorithm, partitionable path) ----------------
__device__ __forceinline__ void d_threefry(uint32_t k0, uint32_t k1,
                                           uint32_t x0, uint32_t x1,
                                           uint32_t& y0, uint32_t& y1) {
    uint32_t k2 = k0 ^ k1 ^ 0x1BD11BDAu;
    x0 += k0; x1 += k1;
#define TFR(r) { x0 += x1; x1 = __funnelshift_l(x1, x1, r); x1 ^= x0; }
    TFR(13) TFR(15) TFR(26) TFR(6)
    x0 += k1; x1 += k2 + 1u;
    TFR(17) TFR(29) TFR(16) TFR(24)
    x0 += k2; x1 += k0 + 2u;
    TFR(13) TFR(15) TFR(26) TFR(6)
    x0 += k0; x1 += k1 + 3u;
    TFR(17) TFR(29) TFR(16) TFR(24)
    x0 += k1; x1 += k2 + 4u;
    TFR(13) TFR(15) TFR(26) TFR(6)
    x0 += k2; x1 += k0 + 5u;
#undef TFR
    y0 = x0; y1 = x1;
}

static inline uint32_t h_rotl(uint32_t x, int r) { return (x << r) | (x >> (32 - r)); }
static void h_threefry(uint32_t k0, uint32_t k1, uint32_t x0, uint32_t x1,
                       uint32_t& y0, uint32_t& y1) {
    uint32_t k2 = k0 ^ k1 ^ 0x1BD11BDAu;
    x0 += k0; x1 += k1;
#define TFR(r) { x0 += x1; x1 = h_rotl(x1, r); x1 ^= x0; }
    TFR(13) TFR(15) TFR(26) TFR(6)
    x0 += k1; x1 += k2 + 1u;
    TFR(17) TFR(29) TFR(16) TFR(24)
    x0 += k2; x1 += k0 + 2u;
    TFR(13) TFR(15) TFR(26) TFR(6)
    x0 += k0; x1 += k1 + 3u;
    TFR(17) TFR(29) TFR(16) TFR(24)
    x0 += k1; x1 += k2 + 4u;
    TFR(13) TFR(15) TFR(26) TFR(6)
    x0 += k2; x1 += k0 + 5u;
#undef TFR
    y0 = x0; y1 = x1;
}

// ---------------- graph prep ----------------
__global__ void k_zero(int n) {
    int i = blockIdx.x * blockDim.x + threadIdx.x;
    if (i < n) { g_deg_out[i] = 0; g_deg_in[i] = 0; }
    if (i < NBLK_SCAN) { g_blk_flag[i] = 0; g_blk_sum[i] = 0; }
}

__global__ void k_degree(const int* __restrict__ src, const int* __restrict__ dst, int e) {
    int i = blockIdx.x * blockDim.x + threadIdx.x;
    if (i < e) {
        atomicAdd(&g_deg_out[src[i]], 1);
        atomicAdd(&g_deg_in[dst[i]], 1);
    }
}

// fused: norms + single-pass exclusive scan (decoupled lookback) -> row_ptr / fill
__global__ void k_scan_norm(int n, int e) {
    __shared__ int s[1024];
    __shared__ int s_prefix;
    int b = blockIdx.x, t = threadIdx.x, i = b * 1024 + t;
    int din = (i < n) ? g_deg_in[i] : 0;
    if (i < n) {
        int a = g_deg_out[i];
        g_norm_src[i] = (a > 0) ? rsqrtf((float)a) : 0.f;
        g_norm_dst[i] = (din > 0) ? rsqrtf((float)din) : 0.f;
    }
    s[t] = din;
    __syncthreads();
    for (int off = 1; off < 1024; off <<= 1) {
        int a = (t >= off) ? s[t - off] : 0;
        __syncthreads();
        s[t] += a;
        __syncthreads();
    }
    if (t == 0) {
        s_prefix = 0;
        g_blk_sum[b] = s[1023];
        __threadfence();
        g_blk_flag[b] = 1;
    }
    __syncthreads();
    if (t < b) {
        while (g_blk_flag[t] == 0) {}
        int v = *((volatile int*)&g_blk_sum[t]);
        atomicAdd(&s_prefix, v);
    }
    __syncthreads();
    int excl = s[t] - din + s_prefix;
    if (i < n) { g_row_ptr[i] = excl; g_fill[i] = excl; }
    if (i == 0) g_row_ptr[n] = e;
}

__global__ void k_csr(const int* __restrict__ src, const int* __restrict__ dst, int e) {
    int i = blockIdx.x * blockDim.x + threadIdx.x;
    if (i < e) {
        int p = atomicAdd(&g_fill[dst[i]], 1);
        g_col[p] = src[i];
    }
}

// U0 = norm_src * x   (float4 elementwise)
__global__ void k_scale_x(const float* __restrict__ x, int n16) {
    int i = blockIdx.x * blockDim.x + threadIdx.x;
    if (i < n16) {
        float ns = g_norm_src[i >> 4];
        float4 v = ((const float4*)x)[i];
        v.x *= ns; v.y *= ns; v.z *= ns; v.w *= ns;
        ((float4*)g_a)[i] = v;
    }
}

// ---------------- packed f32x2 helpers ----------------
__device__ __forceinline__ unsigned long long pk2(float x, float y) {
    unsigned long long r;
    asm("mov.b64 %0, {%1,%2};" : "=l"(r) : "f"(x), "f"(y));
    return r;
}
__device__ __forceinline__ void fma2(unsigned long long& d, unsigned long long a, unsigned long long b) {
    asm("fma.rn.f32x2 %0, %1, %2, %0;" : "+l"(d) : "l"(a), "l"(b));
}
__device__ __forceinline__ float2 upk2(unsigned long long v) {
    float2 r;
    asm("mov.b64 {%0,%1}, %2;" : "=f"(r.x), "=f"(r.y) : "l"(v));
    return r;
}

// ---------------- fused aggregation + tiled GEMM + epilogue ----------------
// Block = 256 threads, 64 nodes.
//  phase 1: warp w gathers nodes base+8w .. base+8w+7 (sequential) into sS[64][66]
//  phase 2: tiled GEMM on smem S (4 rows x 2 cpairs per thread) vs staged W
//  phase 3: epilogue (norm_dst, bias, relu, dropout, next-layer norm_src prescale)
template <int LAYER>
__global__ void __launch_bounds__(256) k_aggemm(const float* __restrict__ U,
                                                float* __restrict__ Unext,
                                                const float* __restrict__ W,
                                                const float* __restrict__ bias,
                                                uint32_t key0, uint32_t key1, int n) {
    __shared__ unsigned long long sW[64 * 32]; // [k][cpair] packed (W[k][2c], W[k][2c+1])
    __shared__ float sS[AGG_NPB * SS_STRIDE];  // [local node][k], padded
    int t = threadIdx.x;
    int base = blockIdx.x * AGG_NPB;
    int w = t >> 5, lane = t & 31;

    // stage W (16KB; one-time per 64 nodes)
    const float2* Wv = (const float2*)W;
#pragma unroll
    for (int q = 0; q < 8; q++) {
        int idx = t + q * 256;
        float2 wv = Wv[idx];
        sW[idx] = pk2(wv.x, wv.y);
    }

    // phase 1: gather-sum 8 nodes per warp (lane = col pair)
    const float2* T2 = (const float2*)U;
#pragma unroll 1
    for (int r = 0; r < 8; r++) {
        int node = base + w * 8 + r;
        float ax = 0.f, ay = 0.f;
        if (node < n) {
            int s = g_row_ptr[node], e = g_row_ptr[node + 1];
            int i = s;
            for (; i + 4 <= e; i += 4) {
                int u0 = g_col[i], u1 = g_col[i + 1], u2 = g_col[i + 2], u3 = g_col[i + 3];
                float2 v0 = T2[u0 * 32 + lane];
                float2 v1 = T2[u1 * 32 + lane];
                float2 v2 = T2[u2 * 32 + lane];
                float2 v3 = T2[u3 * 32 + lane];
                ax += (v0.x + v1.x) + (v2.x + v3.x);
                ay += (v0.y + v1.y) + (v2.y + v3.y);
            }
            for (; i < e; i++) {
                int u = g_col[i];
                float2 v = T2[u * 32 + lane];
                ax += v.x; ay += v.y;
            }
        }
        float* row = &sS[(w * 8 + r) * SS_STRIDE];
        ((float2*)row)[lane] = make_float2(ax, ay);  // cols 2*lane, 2*lane+1
    }
    __syncthreads();

    // phase 2: tiled GEMM. 256 threads = 16 rid x 16 cid.
    // thread: rows rid+16i (i=0..3), cpairs cid+16j (j=0..1).
    int rid = t >> 4;
    int cid = t & 15;
    unsigned long long acc[4][2];
#pragma unroll
    for (int i = 0; i < 4; i++)
#pragma unroll
        for (int j = 0; j < 2; j++) acc[i][j] = 0ull;

#pragma unroll 8
    for (int k = 0; k < 64; k++) {
        unsigned long long a[4], b[2];
#pragma unroll
        for (int i = 0; i < 4; i++) {
            float h = sS[(rid + 16 * i) * SS_STRIDE + k];
            a[i] = pk2(h, h);
        }
#pragma unroll
        for (int j = 0; j < 2; j++) b[j] = sW[k * 32 + cid + 16 * j];
#pragma unroll
        for (int i = 0; i < 4; i++)
#pragma unroll
            for (int j = 0; j < 2; j++) fma2(acc[i][j], a[i], b[j]);
    }

    // phase 3: epilogue
#pragma unroll
    for (int i = 0; i < 4; i++) {
        int node = base + rid + 16 * i;
        if (node < n) {
            float nd = g_norm_dst[node];
            float ns = (LAYER != 2) ? g_norm_src[node] : 0.f;
#pragma unroll
            for (int j = 0; j < 2; j++) {
                int c = cid + 16 * j;
                float2 bb = ((const float2*)bias)[c];
                float2 v = upk2(acc[i][j]);
                float ox = v.x * nd + bb.x;
                float oy = v.y * nd + bb.y;
                if (LAYER != 2) {
                    ox = fmaxf(ox, 0.f);
                    oy = fmaxf(oy, 0.f);
                    uint32_t idx = (uint32_t)node * 64u + 2u * (uint32_t)c;
                    uint32_t y0, y1;
                    d_threefry(key0, key1, 0u, idx, y0, y1);
                    bool keep0 = (((y0 ^ y1) >> 31) == 0u);
                    d_threefry(key0, key1, 0u, idx + 1u, y0, y1);
                    bool keep1 = (((y0 ^ y1) >> 31) == 0u);
                    ox = keep0 ? ox * 2.f * ns : 0.f;
                    oy = keep1 ? oy * 2.f * ns : 0.f;
                }
                ((float2*)Unext)[node * 32 + c] = make_float2(ox, oy);
            }
        }
    }
}

// ---------------- launch ----------------
extern "C" void kernel_launch(void* const* d_in, const int* in_sizes, int n_in,
                              void* d_out, int out_size) {
    const float* x  = (const float*)d_in[0];
    const float* W0 = (const float*)d_in[1];
    const float* b0 = (const float*)d_in[2];
    const float* W1 = (const float*)d_in[3];
    const float* b1 = (const float*)d_in[4];
    const float* W2 = (const float*)d_in[5];
    const float* b2 = (const float*)d_in[6];
    const int*   src = (const int*)d_in[7];
    const int*   dst = (const int*)d_in[8];
    int n = in_sizes[0] / 64;
    int e = in_sizes[7];
    float* out = (float*)d_out;

    int nb = (n + 1023) / 1024;  // <= 98: all scan blocks resident, lookback safe

    uint32_t d0k0, d0k1, d1k0, d1k1;
    h_threefry(0u, 1u, 0u, 0u, d0k0, d0k1);
    h_threefry(0u, 1u, 0u, 1u, d1k0, d1k1);

    float* gA; cudaGetSymbolAddress((void**)&gA, g_a);
    float* gB; cudaGetSymbolAddress((void**)&gB, g_b);

    int aB = (n + AGG_NPB - 1) / AGG_NPB;

    k_zero<<<(n + 255) / 256, 256>>>(n);
    k_degree<<<(e + 255) / 256, 256>>>(src, dst, e);
    k_scan_norm<<<nb, 1024>>>(n, e);
    k_csr<<<(e + 255) / 256, 256>>>(src, dst, e);
    k_scale_x<<<(n * 16 + 255) / 256, 256>>>(x, n * 16);

    k_aggemm<0><<<aB, 256>>>(gA, gB, W0, b0, d0k0, d0k1, n);
    k_aggemm<1><<<aB, 256>>>(gB, gA, W1, b1, d1k0, d1k1, n);
    k_aggemm<2><<<aB, 256>>>(gA, out, W2, b2, 0u, 0u, n);
}

// round 8
// speedup vs baseline: 1.2994x; 1.0086x over previous
#include <cuda_runtime.h>
#include <cstdint>

#define N_MAX 100000
#define E_MAX 1600000
#define NBLK_SCAN 128   // max scan blocks (n/1024 <= 98)
#define AGG_NPB 64      // nodes per fused block
#define SS_STRIDE 66    // padded row stride for sS (floats)

// ---------------- scratch (static device memory; no allocation) ----------------
__device__ int   g_deg_out[N_MAX];
__device__ int   g_deg_in[N_MAX];
__device__ float g_norm_src[N_MAX];
__device__ float g_norm_dst[N_MAX];
__device__ int   g_row_ptr[N_MAX + 1];
__device__ int   g_fill[N_MAX];
__device__ int   g_col[E_MAX];
__device__ float g_a[N_MAX * 64];   // ping: pre-scaled features (norm_src * h)
__device__ float g_b[N_MAX * 64];   // pong
__device__ int g_blk_sum[NBLK_SCAN];
__device__ volatile int g_blk_flag[NBLK_SCAN];

// ---------------- threefry-2x32 (exact JAX algorithm, partitionable path) ----------------
__device__ __forceinline__ void d_threefry(uint32_t k0, uint32_t k1,
                                           uint32_t x0, uint32_t x1,
                                           uint32_t& y0, uint32_t& y1) {
    uint32_t k2 = k0 ^ k1 ^ 0x1BD11BDAu;
    x0 += k0; x1 += k1;
#define TFR(r) { x0 += x1; x1 = __funnelshift_l(x1, x1, r); x1 ^= x0; }
    TFR(13) TFR(15) TFR(26) TFR(6)
    x0 += k1; x1 += k2 + 1u;
    TFR(17) TFR(29) TFR(16) TFR(24)
    x0 += k2; x1 += k0 + 2u;
    TFR(13) TFR(15) TFR(26) TFR(6)
    x0 += k0; x1 += k1 + 3u;
    TFR(17) TFR(29) TFR(16) TFR(24)
    x0 += k1; x1 += k2 + 4u;
    TFR(13) TFR(15) TFR(26) TFR(6)
    x0 += k2; x1 += k0 + 5u;
#undef TFR
    y0 = x0; y1 = x1;
}

static inline uint32_t h_rotl(uint32_t x, int r) { return (x << r) | (x >> (32 - r)); }
static void h_threefry(uint32_t k0, uint32_t k1, uint32_t x0, uint32_t x1,
                       uint32_t& y0, uint32_t& y1) {
    uint32_t k2 = k0 ^ k1 ^ 0x1BD11BDAu;
    x0 += k0; x1 += k1;
#define TFR(r) { x0 += x1; x1 = h_rotl(x1, r); x1 ^= x0; }
    TFR(13) TFR(15) TFR(26) TFR(6)
    x0 += k1; x1 += k2 + 1u;
    TFR(17) TFR(29) TFR(16) TFR(24)
    x0 += k2; x1 += k0 + 2u;
    TFR(13) TFR(15) TFR(26) TFR(6)
    x0 += k0; x1 += k1 + 3u;
    TFR(17) TFR(29) TFR(16) TFR(24)
    x0 += k1; x1 += k2 + 4u;
    TFR(13) TFR(15) TFR(26) TFR(6)
    x0 += k2; x1 += k0 + 5u;
#undef TFR
    y0 = x0; y1 = x1;
}

// ---------------- graph prep ----------------
__global__ void k_zero(int n) {
    int i = blockIdx.x * blockDim.x + threadIdx.x;
    if (i < n) { g_deg_out[i] = 0; g_deg_in[i] = 0; }
    if (i < NBLK_SCAN) { g_blk_flag[i] = 0; g_blk_sum[i] = 0; }
}

__global__ void k_degree(const int* __restrict__ src, const int* __restrict__ dst, int e) {
    int i = blockIdx.x * blockDim.x + threadIdx.x;
    if (i < e) {
        atomicAdd(&g_deg_out[src[i]], 1);
        atomicAdd(&g_deg_in[dst[i]], 1);
    }
}

// fused: norms + single-pass exclusive scan (decoupled lookback) -> row_ptr / fill
// + U0 = norm_src * x  (uses smem-shared norms, coalesced float4)
__global__ void k_scan_norm_scale(const float* __restrict__ x, int n, int e) {
    __shared__ int s[1024];
    __shared__ float snorm[1024];
    __shared__ int s_prefix;
    int b = blockIdx.x, t = threadIdx.x, i = b * 1024 + t;
    int din = (i < n) ? g_deg_in[i] : 0;
    float ns = 0.f;
    if (i < n) {
        int a = g_deg_out[i];
        ns = (a > 0) ? rsqrtf((float)a) : 0.f;
        g_norm_src[i] = ns;
        g_norm_dst[i] = (din > 0) ? rsqrtf((float)din) : 0.f;
    }
    snorm[t] = ns;
    s[t] = din;
    __syncthreads();
    for (int off = 1; off < 1024; off <<= 1) {
        int a = (t >= off) ? s[t - off] : 0;
        __syncthreads();
        s[t] += a;
        __syncthreads();
    }
    if (t == 0) {
        s_prefix = 0;
        g_blk_sum[b] = s[1023];
        __threadfence();
        g_blk_flag[b] = 1;
    }
    __syncthreads();
    if (t < b) {
        while (g_blk_flag[t] == 0) {}
        int v = *((volatile int*)&g_blk_sum[t]);
        atomicAdd(&s_prefix, v);
    }
    __syncthreads();
    int excl = s[t] - din + s_prefix;
    if (i < n) { g_row_ptr[i] = excl; g_fill[i] = excl; }
    if (i == 0) g_row_ptr[n] = e;

    // fused scale: g_a[node][:] = norm_src[node] * x[node][:]
    const float4* x4 = (const float4*)x;
    int f4base = b * 1024 * 16;   // first float4 index of this block's nodes
#pragma unroll
    for (int q = 0; q < 16; q++) {
        int idx = f4base + q * 1024 + t;
        if (idx < n * 16) {
            float nv = snorm[(idx >> 4) - b * 1024];
            float4 v = x4[idx];
            v.x *= nv; v.y *= nv; v.z *= nv; v.w *= nv;
            ((float4*)g_a)[idx] = v;
        }
    }
}

__global__ void k_csr(const int* __restrict__ src, const int* __restrict__ dst, int e) {
    int i = blockIdx.x * blockDim.x + threadIdx.x;
    if (i < e) {
        int p = atomicAdd(&g_fill[dst[i]], 1);
        g_col[p] = src[i];
    }
}

// ---------------- packed f32x2 helpers ----------------
__device__ __forceinline__ unsigned long long pk2(float x, float y) {
    unsigned long long r;
    asm("mov.b64 %0, {%1,%2};" : "=l"(r) : "f"(x), "f"(y));
    return r;
}
__device__ __forceinline__ void fma2(unsigned long long& d, unsigned long long a, unsigned long long b) {
    asm("fma.rn.f32x2 %0, %1, %2, %0;" : "+l"(d) : "l"(a), "l"(b));
}
__device__ __forceinline__ float2 upk2(unsigned long long v) {
    float2 r;
    asm("mov.b64 {%0,%1}, %2;" : "=f"(r.x), "=f"(r.y) : "l"(v));
    return r;
}

// ---------------- fused aggregation + tiled GEMM + epilogue ----------------
// Block = 256 threads, 64 nodes.
//  phase 1: warp w gathers nodes base+8w..base+8w+7 into sS[64][66];
//           iteration r also computes this thread's r-th dropout element pair
//           (threefry ALU ops overlap the in-flight L2 gathers)
//  phase 2: tiled GEMM on smem S (4 rows x 2 cpairs per thread) vs staged W
//  phase 3: epilogue (norm_dst, bias, relu, precomputed dropout, norm_src prescale)
template <int LAYER>
__global__ void __launch_bounds__(256) k_aggemm(const float* __restrict__ U,
                                                float* __restrict__ Unext,
                                                const float* __restrict__ W,
                                                const float* __restrict__ bias,
                                                uint32_t key0, uint32_t key1, int n) {
    __shared__ unsigned long long sW[64 * 32]; // [k][cpair] packed (W[k][2c], W[k][2c+1])
    __shared__ float sS[AGG_NPB * SS_STRIDE];  // [local node][k], padded
    int t = threadIdx.x;
    int base = blockIdx.x * AGG_NPB;
    int w = t >> 5, lane = t & 31;
    int rid = t >> 4;       // epilogue row id
    int cid = t & 15;       // epilogue col-pair id

    // stage W (16KB; one-time per 64 nodes)
    const float2* Wv = (const float2*)W;
#pragma unroll
    for (int q = 0; q < 8; q++) {
        int idx = t + q * 256;
        float2 wv = Wv[idx];
        sW[idx] = pk2(wv.x, wv.y);
    }

    // phase 1: gather-sum 8 nodes per warp (lane = col pair); dropout masks interleaved
    uint32_t keepmask = 0;  // bit 2*r / 2*r+1 : keep bits for epilogue element pair r
    const float2* T2 = (const float2*)U;
#pragma unroll 1
    for (int r = 0; r < 8; r++) {
        int node = base + w * 8 + r;
        float ax = 0.f, ay = 0.f;
        int s = 0, e = 0;
        if (node < n) { s = g_row_ptr[node]; e = g_row_ptr[node + 1]; }

        // dropout threefry for epilogue element pair r: node base+rid+16*(r>>1),
        // cols 2*(cid+16*(r&1)) .. +1. ALU-pipe work overlapping the gathers below.
        if (LAYER != 2) {
            int en = base + rid + 16 * (r >> 1);
            int ec = cid + 16 * (r & 1);
            uint32_t idx = (uint32_t)en * 64u + 2u * (uint32_t)ec;
            uint32_t y0, y1, z0, z1;
            d_threefry(key0, key1, 0u, idx, y0, y1);
            d_threefry(key0, key1, 0u, idx + 1u, z0, z1);
            keepmask |= (1u ^ ((y0 ^ y1) >> 31)) << (2 * r);
            keepmask |= (1u ^ ((z0 ^ z1) >> 31)) << (2 * r + 1);
        }

        int i = s;
        for (; i + 4 <= e; i += 4) {
            int u0 = g_col[i], u1 = g_col[i + 1], u2 = g_col[i + 2], u3 = g_col[i + 3];
            float2 v0 = T2[u0 * 32 + lane];
            float2 v1 = T2[u1 * 32 + lane];
            float2 v2 = T2[u2 * 32 + lane];
            float2 v3 = T2[u3 * 32 + lane];
            ax += (v0.x + v1.x) + (v2.x + v3.x);
            ay += (v0.y + v1.y) + (v2.y + v3.y);
        }
        for (; i < e; i++) {
            int u = g_col[i];
            float2 v = T2[u * 32 + lane];
            ax += v.x; ay += v.y;
        }
        float* row = &sS[(w * 8 + r) * SS_STRIDE];
        ((float2*)row)[lane] = make_float2(ax, ay);  // cols 2*lane, 2*lane+1
    }
    __syncthreads();

    // phase 2: tiled GEMM. thread: rows rid+16i (i=0..3), cpairs cid+16j (j=0..1).
    unsigned long long acc[4][2];
#pragma unroll
    for (int i = 0; i < 4; i++)
#pragma unroll
        for (int j = 0; j < 2; j++) acc[i][j] = 0ull;

#pragma unroll 8
    for (int k = 0; k < 64; k++) {
        unsigned long long a[4], b[2];
#pragma unroll
        for (int i = 0; i < 4; i++) {
            float h = sS[(rid + 16 * i) * SS_STRIDE + k];
            a[i] = pk2(h, h);
        }
#pragma unroll
        for (int j = 0; j < 2; j++) b[j] = sW[k * 32 + cid + 16 * j];
#pragma unroll
        for (int i = 0; i < 4; i++)
#pragma unroll
            for (int j = 0; j < 2; j++) fma2(acc[i][j], a[i], b[j]);
    }

    // phase 3: epilogue (element pair r = 2*i + j  ->  keepmask bits 2r, 2r+1)
#pragma unroll
    for (int i = 0; i < 4; i++) {
        int node = base + rid + 16 * i;
        if (node < n) {
            float nd = g_norm_dst[node];
            float ns = (LAYER != 2) ? g_norm_src[node] : 0.f;
#pragma unroll
            for (int j = 0; j < 2; j++) {
                int c = cid + 16 * j;
                float2 bb = ((const float2*)bias)[c];
                float2 v = upk2(acc[i][j]);
                float ox = v.x * nd + bb.x;
                float oy = v.y * nd + bb.y;
                if (LAYER != 2) {
                    ox = fmaxf(ox, 0.f);
                    oy = fmaxf(oy, 0.f);
                    int r = 2 * i + j;
                    bool keep0 = (keepmask >> (2 * r)) & 1u;
                    bool keep1 = (keepmask >> (2 * r + 1)) & 1u;
                    ox = keep0 ? ox * 2.f * ns : 0.f;
                    oy = keep1 ? oy * 2.f * ns : 0.f;
                }
                ((float2*)Unext)[node * 32 + c] = make_float2(ox, oy);
            }
        }
    }
}

// ---------------- launch ----------------
extern "C" void kernel_launch(void* const* d_in, const int* in_sizes, int n_in,
                              void* d_out, int out_size) {
    const float* x  = (const float*)d_in[0];
    const float* W0 = (const float*)d_in[1];
    const float* b0 = (const float*)d_in[2];
    const float* W1 = (const float*)d_in[3];
    const float* b1 = (const float*)d_in[4];
    const float* W2 = (const float*)d_in[5];
    const float* b2 = (const float*)d_in[6];
    const int*   src = (const int*)d_in[7];
    const int*   dst = (const int*)d_in[8];
    int n = in_sizes[0] / 64;
    int e = in_sizes[7];
    float* out = (float*)d_out;

    int nb = (n + 1023) / 1024;  // <= 98: all scan blocks resident, lookback safe

    uint32_t d0k0, d0k1, d1k0, d1k1;
    h_threefry(0u, 1u, 0u, 0u, d0k0, d0k1);
    h_threefry(0u, 1u, 0u, 1u, d1k0, d1k1);

    float* gA; cudaGetSymbolAddress((void**)&gA, g_a);
    float* gB; cudaGetSymbolAddress((void**)&gB, g_b);

    int aB = (n + AGG_NPB - 1) / AGG_NPB;

    k_zero<<<(n + 255) / 256, 256>>>(n);
    k_degree<<<(e + 255) / 256, 256>>>(src, dst, e);
    k_scan_norm_scale<<<nb, 1024>>>(x, n, e);
    k_csr<<<(e + 255) / 256, 256>>>(src, dst, e);

    k_aggemm<0><<<aB, 256>>>(gA, gB, W0, b0, d0k0, d0k1, n);
    k_aggemm<1><<<aB, 256>>>(gB, gA, W1, b1, d1k0, d1k1, n);
    k_aggemm<2><<<aB, 256>>>(gA, out, W2, b2, 0u, 0u, n);
}